// round 2
// baseline (speedup 1.0000x reference)
#include <cuda_runtime.h>
#include <math.h>

#define EMBED 1024
#define HEADS 16
#define DKH 64
#define BATCH 2
#define SEQ 2048

// Scratch (allocation-free rule: __device__ globals)
__device__ float g_q[BATCH * HEADS * SEQ * DKH];
__device__ float g_k[BATCH * HEADS * SEQ * DKH];
__device__ float g_v[BATCH * HEADS * SEQ * DKH];
__device__ float g_attn[BATCH * SEQ * EMBED];

// ---------------------------------------------------------------------------
// GEMM: C = A[4096,1024] @ W[1024,1024]
// MODE 0: plain row-major store (final projection -> d_out)
// MODE 1: RoPE + scatter to [B,H,S,DKH]  (q, k)
// MODE 2: scatter to [B,H,S,DKH] only    (v)
// 64x64 tile, BK=16, 256 threads, 4x4 register tile
// ---------------------------------------------------------------------------
template <int MODE>
__global__ void __launch_bounds__(256) gemm_kernel(const float* __restrict__ A,
                                                   const float* __restrict__ W,
                                                   float* __restrict__ C) {
    const int N = EMBED, K = EMBED;
    __shared__ float As[16][68];  // [k][m] transposed
    __shared__ float Bs[16][68];  // [k][n]

    const int t = threadIdx.x;
    const int tx = t & 15, ty = t >> 4;
    const int bm = blockIdx.y * 64, bn = blockIdx.x * 64;

    float acc[4][4];
#pragma unroll
    for (int i = 0; i < 4; i++)
#pragma unroll
        for (int j = 0; j < 4; j++) acc[i][j] = 0.f;

    const int ar = t >> 2, ac = (t & 3) * 4;
    const int br = t >> 4, bc = (t & 15) * 4;
    const float* Ap = A + (size_t)(bm + ar) * K + ac;
    const float* Wp = W + (size_t)br * N + bn + bc;

    for (int k0 = 0; k0 < K; k0 += 16) {
        float4 av = *(const float4*)(Ap + k0);
        As[ac + 0][ar] = av.x;
        As[ac + 1][ar] = av.y;
        As[ac + 2][ar] = av.z;
        As[ac + 3][ar] = av.w;
        *(float4*)&Bs[br][bc] = *(const float4*)(Wp + (size_t)k0 * N);
        __syncthreads();
#pragma unroll
        for (int kk = 0; kk < 16; kk++) {
            float4 a4 = *(const float4*)&As[kk][ty * 4];
            float4 b4 = *(const float4*)&Bs[kk][tx * 4];
            float a[4] = {a4.x, a4.y, a4.z, a4.w};
            float b[4] = {b4.x, b4.y, b4.z, b4.w};
#pragma unroll
            for (int i = 0; i < 4; i++)
#pragma unroll
                for (int j = 0; j < 4; j++)
                    acc[i][j] = fmaf(a[i], b[j], acc[i][j]);
        }
        __syncthreads();
    }

    if (MODE == 0) {
#pragma unroll
        for (int i = 0; i < 4; i++) {
            float4 v4 = make_float4(acc[i][0], acc[i][1], acc[i][2], acc[i][3]);
            *(float4*)&C[(size_t)(bm + ty * 4 + i) * N + bn + tx * 4] = v4;
        }
    } else {
#pragma unroll
        for (int i = 0; i < 4; i++) {
            int m = bm + ty * 4 + i;
            int b = m / SEQ, s = m - b * SEQ;
#pragma unroll
            for (int jj = 0; jj < 4; jj += 2) {
                int n = bn + tx * 4 + jj;
                int h = n >> 6, d = n & 63;
                float oe = acc[i][jj], oo = acc[i][jj + 1];
                if (MODE == 1) {
                    // interleaved RoPE: pair (2p, 2p+1), angle = s * inv_freq[p]
                    int p = d >> 1;
                    float inv = (float)(1.0 / pow(10000.0, (double)(2 * p) / 64.0));
                    float ang = (float)s * inv;
                    float cs = cosf(ang), sn = sinf(ang);
                    float ne = oe * cs - oo * sn;
                    float no = oo * cs + oe * sn;
                    oe = ne;
                    oo = no;
                }
                size_t dst = (((size_t)b * HEADS + h) * SEQ + s) * DKH + d;
                C[dst] = oe;
                C[dst + 1] = oo;
            }
        }
    }
}

// ---------------------------------------------------------------------------
// Flash attention, fp32, causal. Q/K/V in [B*H][S][DKH].
// Per block: 64 q-rows, loop over 32-row K/V tiles with online softmax.
// 256 threads as 16x16: rows r = ty*4+i, score cols c = tx*2+jj,
// output dims d = tx*4+jj.
// ---------------------------------------------------------------------------
__global__ void __launch_bounds__(256) flash_kernel(const float* __restrict__ Q,
                                                    const float* __restrict__ Kk,
                                                    const float* __restrict__ V,
                                                    float* __restrict__ Out) {
    __shared__ float qst[64][68];  // [d][r]
    __shared__ float kst[64][36];  // [d][c]
    __shared__ float vsm[32][68];  // [c][d]
    __shared__ float pst[32][68];  // [c][r]

    const int t = threadIdx.x;
    const int tx = t & 15, ty = t >> 4;
    const int qi = gridDim.x - 1 - blockIdx.x;  // launch long blocks first
    const int bh = blockIdx.y;
    const int b = bh >> 4, h = bh & 15;

    const float* Qb = Q + ((size_t)bh * SEQ + (size_t)qi * 64) * DKH;
    const float* Kb = Kk + (size_t)bh * SEQ * DKH;
    const float* Vb = V + (size_t)bh * SEQ * DKH;

#pragma unroll
    for (int i = 0; i < 16; i++) {
        int lin = t + 256 * i;
        qst[lin & 63][lin >> 6] = Qb[lin];
    }

    float mi[4], li[4], o[4][4];
#pragma unroll
    for (int i = 0; i < 4; i++) {
        mi[i] = -INFINITY;
        li[i] = 0.f;
#pragma unroll
        for (int j = 0; j < 4; j++) o[i][j] = 0.f;
    }

    const int ntiles = 2 * qi + 2;
    for (int j = 0; j < ntiles; j++) {
        __syncthreads();  // previous PV done before overwriting K/V tiles
#pragma unroll
        for (int i = 0; i < 8; i++) {
            int lin = t + 256 * i;
            int c = lin >> 6, d = lin & 63;
            kst[d][c] = Kb[(size_t)j * 32 * DKH + lin];
            vsm[c][d] = Vb[(size_t)j * 32 * DKH + lin];
        }
        __syncthreads();

        // scores: S = Q K^T
        float sc[4][2];
#pragma unroll
        for (int i = 0; i < 4; i++) {
            sc[i][0] = 0.f;
            sc[i][1] = 0.f;
        }
#pragma unroll
        for (int d = 0; d < 64; d++) {
            float4 a4 = *(const float4*)&qst[d][ty * 4];
            float2 b2 = *(const float2*)&kst[d][tx * 2];
            float a[4] = {a4.x, a4.y, a4.z, a4.w};
#pragma unroll
            for (int i = 0; i < 4; i++) {
                sc[i][0] = fmaf(a[i], b2.x, sc[i][0]);
                sc[i][1] = fmaf(a[i], b2.y, sc[i][1]);
            }
        }

        // scale + causal mask
        const int gr = qi * 64 + ty * 4;
        const int gc = j * 32 + tx * 2;
#pragma unroll
        for (int i = 0; i < 4; i++)
#pragma unroll
            for (int jj = 0; jj < 2; jj++) {
                if (gc + jj > gr + i)
                    sc[i][jj] = -INFINITY;
                else
                    sc[i][jj] *= 0.125f;  // 1/sqrt(64)
            }

        // online softmax, row groups = 16 lanes
#pragma unroll
        for (int i = 0; i < 4; i++) {
            float rm = fmaxf(sc[i][0], sc[i][1]);
#pragma unroll
            for (int off = 8; off; off >>= 1)
                rm = fmaxf(rm, __shfl_xor_sync(0xffffffffu, rm, off, 16));
            float mn = fmaxf(mi[i], rm);
            float alpha = expf(mi[i] - mn);
            float p0 = expf(sc[i][0] - mn);
            float p1 = expf(sc[i][1] - mn);
            float rs = p0 + p1;
#pragma unroll
            for (int off = 8; off; off >>= 1)
                rs += __shfl_xor_sync(0xffffffffu, rs, off, 16);
            li[i] = li[i] * alpha + rs;
            mi[i] = mn;
#pragma unroll
            for (int jj = 0; jj < 4; jj++) o[i][jj] *= alpha;
            pst[tx * 2 + 0][ty * 4 + i] = p0;
            pst[tx * 2 + 1][ty * 4 + i] = p1;
        }
        __syncthreads();

        // O += P V
#pragma unroll
        for (int c = 0; c < 32; c++) {
            float4 p4 = *(const float4*)&pst[c][ty * 4];
            float4 v4 = *(const float4*)&vsm[c][tx * 4];
            float p[4] = {p4.x, p4.y, p4.z, p4.w};
            float v[4] = {v4.x, v4.y, v4.z, v4.w};
#pragma unroll
            for (int i = 0; i < 4; i++)
#pragma unroll
                for (int jj = 0; jj < 4; jj++)
                    o[i][jj] = fmaf(p[i], v[jj], o[i][jj]);
        }
    }

    // epilogue: normalize, write to [B,S,E] layout for the output GEMM
#pragma unroll
    for (int i = 0; i < 4; i++) {
        int grow = qi * 64 + ty * 4 + i;
        float inv = 1.f / li[i];
        size_t base = ((size_t)b * SEQ + grow) * EMBED + h * DKH + tx * 4;
#pragma unroll
        for (int jj = 0; jj < 4; jj++) Out[base + jj] = o[i][jj] * inv;
    }
}

extern "C" void kernel_launch(void* const* d_in, const int* in_sizes, int n_in,
                              void* d_out, int out_size) {
    (void)in_sizes;
    (void)n_in;
    (void)out_size;
    const float* x = (const float*)d_in[0];
    const float* wq = (const float*)d_in[1];
    const float* wk = (const float*)d_in[2];
    const float* wv = (const float*)d_in[3];
    const float* wo = (const float*)d_in[4];
    float* out = (float*)d_out;

    float *q, *k, *v, *attn;
    cudaGetSymbolAddress((void**)&q, g_q);
    cudaGetSymbolAddress((void**)&k, g_k);
    cudaGetSymbolAddress((void**)&v, g_v);
    cudaGetSymbolAddress((void**)&attn, g_attn);

    dim3 gg(EMBED / 64, (BATCH * SEQ) / 64);  // (16, 64)
    gemm_kernel<1><<<gg, 256>>>(x, wq, q);
    gemm_kernel<1><<<gg, 256>>>(x, wk, k);
    gemm_kernel<2><<<gg, 256>>>(x, wv, v);
    flash_kernel<<<dim3(SEQ / 64, BATCH * HEADS), 256>>>(q, k, v, attn);
    gemm_kernel<0><<<gg, 256>>>(attn, wo, out);
}

// round 4
// speedup vs baseline: 1.6950x; 1.6950x over previous
#include <cuda_runtime.h>
#include <math.h>
#include <stdint.h>

#define EMBED 1024
#define HEADS 16
#define DKH 64
#define BATCH 2
#define SEQ 2048
#define MTOT (BATCH * SEQ)  // 4096

// ---- mma.sync tf32 GEMM tiling ----
#define BK 32
#define NCH (EMBED / BK)        // 32 k-chunks
#define ASTR 36                 // A smem stride (floats), conflict-free
#define BSTR 136                // B smem stride (floats), conflict-free
#define ABYTES (128 * ASTR * 4) // 18432
#define BBYTES (BK * BSTR * 4)  // 17408
#define STAGEB (ABYTES + BBYTES)// 35840 per pipeline stage
#define GSMEM 73728             // max(2*STAGEB=71680, 8 warps * 64*36*4 = 73728)

// Scratch (allocation-free rule: __device__ globals)
__device__ float g_q[(size_t)BATCH * HEADS * SEQ * DKH];
__device__ float g_k[(size_t)BATCH * HEADS * SEQ * DKH];
__device__ float g_v[(size_t)BATCH * HEADS * SEQ * DKH];
__device__ float g_attn[(size_t)MTOT * EMBED];
__device__ float2 g_rope[(size_t)SEQ * 32];  // {cos, sin} per (pos, pair)

// ---------------------------------------------------------------------------
// helpers
// ---------------------------------------------------------------------------
__device__ __forceinline__ uint32_t su32(const void* p) {
    uint32_t a;
    asm("{ .reg .u64 t; cvta.to.shared.u64 t, %1; cvt.u32.u64 %0, t; }"
        : "=r"(a) : "l"(p));
    return a;
}

__device__ __forceinline__ void cp16(uint32_t dst, const void* src) {
    asm volatile("cp.async.cg.shared.global [%0], [%1], 16;" :: "r"(dst), "l"(src));
}

__device__ __forceinline__ uint32_t cvt_tf32(float x) {
    uint32_t r;
    asm("cvt.rna.tf32.f32 %0, %1;" : "=r"(r) : "f"(x));
    return r;
}

__device__ __forceinline__ void mma8(float* d, const uint32_t* a, const uint32_t* b) {
    asm volatile(
        "mma.sync.aligned.m16n8k8.row.col.f32.tf32.tf32.f32 "
        "{%0,%1,%2,%3}, {%4,%5,%6,%7}, {%8,%9}, {%0,%1,%2,%3};"
        : "+f"(d[0]), "+f"(d[1]), "+f"(d[2]), "+f"(d[3])
        : "r"(a[0]), "r"(a[1]), "r"(a[2]), "r"(a[3]), "r"(b[0]), "r"(b[1]));
}

// ---------------------------------------------------------------------------
// RoPE table: g_rope[s*32+p] = {cos, sin} of s * 10000^(-2p/64)
// ---------------------------------------------------------------------------
__global__ void rope_table_kernel() {
    int idx = blockIdx.x * 256 + threadIdx.x;
    int s = idx >> 5, p = idx & 31;
    double inv = 1.0 / pow(10000.0, (double)(2 * p) / 64.0);
    float ang = (float)s * (float)inv;
    g_rope[idx] = make_float2(cosf(ang), sinf(ang));
}

// ---------------------------------------------------------------------------
// mma.sync tf32 GEMM: C[4096,1024] = A @ W, W row-major [K][N] (native layout).
// CTA 128x128, BK=32, 256 threads = 8 warps (2x4), warp tile 64x32.
// MODE 1: blockIdx.z selects wq/wk/wv; RoPE for z<2; scatter to [B,H,S,DKH].
// MODE 0: wo projection, plain [M][N] store.
// ---------------------------------------------------------------------------
template <int MODE>
__global__ void __launch_bounds__(256) gemm_mma(const float* __restrict__ A,
                                                const float* __restrict__ w0,
                                                const float* __restrict__ w1,
                                                const float* __restrict__ w2,
                                                float* __restrict__ d0,
                                                float* __restrict__ d1,
                                                float* __restrict__ d2) {
    extern __shared__ float sm[];

    const int tid = threadIdx.x;
    const int lane = tid & 31, wid = tid >> 5;
    const int wm = wid >> 2, wn = wid & 3;  // warp grid 2x4
    const int gr = lane >> 2, gc = lane & 3;
    const int n0 = blockIdx.x * 128;
    const int m0 = blockIdx.y * 128;

    const float* W;
    float* dst;
    int rope;
    if (MODE == 1) {
        int z = blockIdx.z;
        W = z == 0 ? w0 : (z == 1 ? w1 : w2);
        dst = z == 0 ? d0 : (z == 1 ? d1 : d2);
        rope = (z < 2);
    } else {
        W = w0;
        dst = d0;
        rope = 0;
    }

    const uint32_t smb = su32(sm);

    // ---- fill K-chunk kc into stage s ----
    auto fill = [&](int s, int kc) {
        uint32_t ab = smb + (uint32_t)s * STAGEB;
        uint32_t bb = ab + ABYTES;
#pragma unroll
        for (int it = 0; it < 4; it++) {  // A: 128 rows x 8 float4-chunks
            int idx = tid + it * 256;
            int r = idx >> 3, c4 = idx & 7;
            cp16(ab + (uint32_t)(r * (ASTR * 4) + c4 * 16),
                 A + (size_t)(m0 + r) * EMBED + kc + c4 * 4);
        }
#pragma unroll
        for (int it = 0; it < 4; it++) {  // B: 32 rows x 32 float4-chunks
            int idx = tid + it * 256;
            int r = idx >> 5, c4 = idx & 31;
            cp16(bb + (uint32_t)(r * (BSTR * 4) + c4 * 16),
                 W + (size_t)(kc + r) * EMBED + n0 + c4 * 4);
        }
        asm volatile("cp.async.commit_group;" ::: "memory");
    };

    float acc[4][4][4];
#pragma unroll
    for (int mi = 0; mi < 4; mi++)
#pragma unroll
        for (int ni = 0; ni < 4; ni++)
#pragma unroll
            for (int r = 0; r < 4; r++) acc[mi][ni][r] = 0.f;

    fill(0, 0);

    for (int i = 0; i < NCH; i++) {
        if (i + 1 < NCH) {
            fill((i + 1) & 1, (i + 1) * BK);
            asm volatile("cp.async.wait_group 1;" ::: "memory");
        } else {
            asm volatile("cp.async.wait_group 0;" ::: "memory");
        }
        __syncthreads();

        const float* Asb = sm + (i & 1) * (STAGEB / 4);
        const float* Bsb = Asb + 128 * ASTR;

#pragma unroll
        for (int ks = 0; ks < 4; ks++) {
            const int kb = ks * 8;
            uint32_t af[4][4], bf[4][2];
#pragma unroll
            for (int mi = 0; mi < 4; mi++) {
                int r0 = wm * 64 + mi * 16 + gr;
                af[mi][0] = cvt_tf32(Asb[r0 * ASTR + kb + gc]);
                af[mi][1] = cvt_tf32(Asb[(r0 + 8) * ASTR + kb + gc]);
                af[mi][2] = cvt_tf32(Asb[r0 * ASTR + kb + gc + 4]);
                af[mi][3] = cvt_tf32(Asb[(r0 + 8) * ASTR + kb + gc + 4]);
            }
#pragma unroll
            for (int ni = 0; ni < 4; ni++) {
                int c0 = wn * 32 + ni * 8 + gr;
                bf[ni][0] = cvt_tf32(Bsb[(kb + gc) * BSTR + c0]);
                bf[ni][1] = cvt_tf32(Bsb[(kb + gc + 4) * BSTR + c0]);
            }
#pragma unroll
            for (int mi = 0; mi < 4; mi++)
#pragma unroll
                for (int ni = 0; ni < 4; ni++)
                    mma8(acc[mi][ni], af[mi], bf[ni]);
        }
        __syncthreads();
    }

    // ---- epilogue ----
    if (rope) {
#pragma unroll
        for (int mi = 0; mi < 4; mi++)
#pragma unroll
            for (int h2 = 0; h2 < 2; h2++) {
                int row = m0 + wm * 64 + mi * 16 + gr + h2 * 8;
                int s = row & (SEQ - 1);
#pragma unroll
                for (int ni = 0; ni < 4; ni++) {
                    int col = n0 + wn * 32 + ni * 8 + gc * 2;
                    int p = (col & 63) >> 1;
                    float2 cs = g_rope[(size_t)s * 32 + p];
                    float e = acc[mi][ni][h2 * 2 + 0];
                    float o = acc[mi][ni][h2 * 2 + 1];
                    acc[mi][ni][h2 * 2 + 0] = e * cs.x - o * cs.y;
                    acc[mi][ni][h2 * 2 + 1] = o * cs.x + e * cs.y;
                }
            }
    }

    // stage warp tile 64x32 -> smem (stride 36 keeps float4 reads aligned)
    float* stg = sm + wid * (64 * 36);
#pragma unroll
    for (int mi = 0; mi < 4; mi++)
#pragma unroll
        for (int ni = 0; ni < 4; ni++)
#pragma unroll
            for (int h2 = 0; h2 < 2; h2++) {
                int rl = mi * 16 + gr + h2 * 8;
                int cl = ni * 8 + gc * 2;
                *(float2*)&stg[rl * 36 + cl] =
                    make_float2(acc[mi][ni][h2 * 2], acc[mi][ni][h2 * 2 + 1]);
            }
    __syncwarp();

    const int lr = lane >> 3, c4 = lane & 7;
    if (MODE == 0) {
#pragma unroll
        for (int it = 0; it < 16; it++) {
            int rl = it * 4 + lr;
            float4 v = *(float4*)&stg[rl * 36 + c4 * 4];
            int row = m0 + wm * 64 + rl;
            *(float4*)&dst[(size_t)row * EMBED + n0 + wn * 32 + c4 * 4] = v;
        }
    } else {
        const int ncol = n0 + wn * 32;
        const int h = ncol >> 6, dbase = ncol & 63;
#pragma unroll
        for (int it = 0; it < 16; it++) {
            int rl = it * 4 + lr;
            float4 v = *(float4*)&stg[rl * 36 + c4 * 4];
            int row = m0 + wm * 64 + rl;
            int b = row >> 11;
            int s = row & (SEQ - 1);
            *(float4*)&dst[(((size_t)(b * HEADS + h)) * SEQ + s) * DKH + dbase + c4 * 4] = v;
        }
    }
}

// ---------------------------------------------------------------------------
// Flash attention, fp32, causal (unchanged from the passing R2 kernel).
// ---------------------------------------------------------------------------
__global__ void __launch_bounds__(256) flash_kernel(const float* __restrict__ Q,
                                                    const float* __restrict__ Kk,
                                                    const float* __restrict__ V,
                                                    float* __restrict__ Out) {
    __shared__ float qst[64][68];
    __shared__ float kst[64][36];
    __shared__ float vsm[32][68];
    __shared__ float pst[32][68];

    const int t = threadIdx.x;
    const int tx = t & 15, ty = t >> 4;
    const int qi = gridDim.x - 1 - blockIdx.x;
    const int bh = blockIdx.y;
    const int b = bh >> 4, h = bh & 15;

    const float* Qb = Q + ((size_t)bh * SEQ + (size_t)qi * 64) * DKH;
    const float* Kb = Kk + (size_t)bh * SEQ * DKH;
    const float* Vb = V + (size_t)bh * SEQ * DKH;

#pragma unroll
    for (int i = 0; i < 16; i++) {
        int lin = t + 256 * i;
        qst[lin & 63][lin >> 6] = Qb[lin];
    }

    float mi[4], li[4], o[4][4];
#pragma unroll
    for (int i = 0; i < 4; i++) {
        mi[i] = -INFINITY;
        li[i] = 0.f;
#pragma unroll
        for (int j = 0; j < 4; j++) o[i][j] = 0.f;
    }

    const int ntiles = 2 * qi + 2;
    for (int j = 0; j < ntiles; j++) {
        __syncthreads();
#pragma unroll
        for (int i = 0; i < 8; i++) {
            int lin = t + 256 * i;
            int c = lin >> 6, d = lin & 63;
            kst[d][c] = Kb[(size_t)j * 32 * DKH + lin];
            vsm[c][d] = Vb[(size_t)j * 32 * DKH + lin];
        }
        __syncthreads();

        float sc[4][2];
#pragma unroll
        for (int i = 0; i < 4; i++) {
            sc[i][0] = 0.f;
            sc[i][1] = 0.f;
        }
#pragma unroll
        for (int d = 0; d < 64; d++) {
            float4 a4 = *(const float4*)&qst[d][ty * 4];
            float2 b2 = *(const float2*)&kst[d][tx * 2];
            float a[4] = {a4.x, a4.y, a4.z, a4.w};
#pragma unroll
            for (int i = 0; i < 4; i++) {
                sc[i][0] = fmaf(a[i], b2.x, sc[i][0]);
                sc[i][1] = fmaf(a[i], b2.y, sc[i][1]);
            }
        }

        const int gr = qi * 64 + ty * 4;
        const int gc = j * 32 + tx * 2;
#pragma unroll
        for (int i = 0; i < 4; i++)
#pragma unroll
            for (int jj = 0; jj < 2; jj++) {
                if (gc + jj > gr + i)
                    sc[i][jj] = -INFINITY;
                else
                    sc[i][jj] *= 0.125f;
            }

#pragma unroll
        for (int i = 0; i < 4; i++) {
            float rm = fmaxf(sc[i][0], sc[i][1]);
#pragma unroll
            for (int off = 8; off; off >>= 1)
                rm = fmaxf(rm, __shfl_xor_sync(0xffffffffu, rm, off, 16));
            float mn = fmaxf(mi[i], rm);
            float alpha = expf(mi[i] - mn);
            float p0 = expf(sc[i][0] - mn);
            float p1 = expf(sc[i][1] - mn);
            float rs = p0 + p1;
#pragma unroll
            for (int off = 8; off; off >>= 1)
                rs += __shfl_xor_sync(0xffffffffu, rs, off, 16);
            li[i] = li[i] * alpha + rs;
            mi[i] = mn;
#pragma unroll
            for (int jj = 0; jj < 4; jj++) o[i][jj] *= alpha;
            pst[tx * 2 + 0][ty * 4 + i] = p0;
            pst[tx * 2 + 1][ty * 4 + i] = p1;
        }
        __syncthreads();

#pragma unroll
        for (int c = 0; c < 32; c++) {
            float4 p4 = *(const float4*)&pst[c][ty * 4];
            float4 v4 = *(const float4*)&vsm[c][tx * 4];
            float p[4] = {p4.x, p4.y, p4.z, p4.w};
            float v[4] = {v4.x, v4.y, v4.z, v4.w};
#pragma unroll
            for (int i = 0; i < 4; i++)
#pragma unroll
                for (int jj = 0; jj < 4; jj++)
                    o[i][jj] = fmaf(p[i], v[jj], o[i][jj]);
        }
    }

#pragma unroll
    for (int i = 0; i < 4; i++) {
        int grow = qi * 64 + ty * 4 + i;
        float inv = 1.f / li[i];
        size_t base = ((size_t)b * SEQ + grow) * EMBED + h * DKH + tx * 4;
#pragma unroll
        for (int jj = 0; jj < 4; jj++) Out[base + jj] = o[i][jj] * inv;
    }
}

extern "C" void kernel_launch(void* const* d_in, const int* in_sizes, int n_in,
                              void* d_out, int out_size) {
    (void)in_sizes;
    (void)n_in;
    (void)out_size;
    const float* x = (const float*)d_in[0];
    const float* wq = (const float*)d_in[1];
    const float* wk = (const float*)d_in[2];
    const float* wv = (const float*)d_in[3];
    const float* wo = (const float*)d_in[4];
    float* out = (float*)d_out;

    float *q, *k, *v, *attn;
    cudaGetSymbolAddress((void**)&q, g_q);
    cudaGetSymbolAddress((void**)&k, g_k);
    cudaGetSymbolAddress((void**)&v, g_v);
    cudaGetSymbolAddress((void**)&attn, g_attn);

    cudaFuncSetAttribute(gemm_mma<1>, cudaFuncAttributeMaxDynamicSharedMemorySize, GSMEM);
    cudaFuncSetAttribute(gemm_mma<0>, cudaFuncAttributeMaxDynamicSharedMemorySize, GSMEM);

    rope_table_kernel<<<SEQ * 32 / 256, 256>>>();
    gemm_mma<1><<<dim3(EMBED / 128, MTOT / 128, 3), 256, GSMEM>>>(x, wq, wk, wv, q, k, v);
    flash_kernel<<<dim3(SEQ / 64, BATCH * HEADS), 256>>>(q, k, v, attn);
    gemm_mma<0><<<dim3(EMBED / 128, MTOT / 128, 1), 256, GSMEM>>>(attn, wo, nullptr, nullptr,
                                                                  out, nullptr, nullptr);
}

// round 5
// speedup vs baseline: 3.5787x; 2.1114x over previous
#include <cuda_runtime.h>
#include <math.h>
#include <stdint.h>

#define EMBED 1024
#define HEADS 16
#define DKH 64
#define BATCH 2
#define SEQ 2048
#define MTOT (BATCH * SEQ)  // 4096

// ---- mma.sync tf32 GEMM tiling ----
#define BK 32
#define NCH (EMBED / BK)
#define ASTR 36
#define BSTR 136
#define ABYTES (128 * ASTR * 4)
#define BBYTES (BK * BSTR * 4)
#define STAGEB (ABYTES + BBYTES)
#define GSMEM 73728

// ---- flash-TC smem layout (floats) ----
#define FK0 0
#define FK1 4352
#define FV0 8704
#define FV1 13312
#define FP 17920
#define FSMEM ((FP + 4352) * 4)  // 89088 bytes

// Scratch (allocation-free rule: __device__ globals)
__device__ float g_q[(size_t)BATCH * HEADS * SEQ * DKH];
__device__ float g_k[(size_t)BATCH * HEADS * SEQ * DKH];
__device__ float g_v[(size_t)BATCH * HEADS * SEQ * DKH];
__device__ float g_attn[(size_t)MTOT * EMBED];
__device__ float2 g_rope[(size_t)SEQ * 32];

// ---------------------------------------------------------------------------
// helpers
// ---------------------------------------------------------------------------
__device__ __forceinline__ uint32_t su32(const void* p) {
    uint32_t a;
    asm("{ .reg .u64 t; cvta.to.shared.u64 t, %1; cvt.u32.u64 %0, t; }"
        : "=r"(a) : "l"(p));
    return a;
}

__device__ __forceinline__ void cp16(uint32_t dst, const void* src) {
    asm volatile("cp.async.cg.shared.global [%0], [%1], 16;" :: "r"(dst), "l"(src));
}

__device__ __forceinline__ uint32_t cvt_tf32(float x) {
    uint32_t r;
    asm("cvt.rna.tf32.f32 %0, %1;" : "=r"(r) : "f"(x));
    return r;
}

__device__ __forceinline__ float tfr(float x) {  // tf32-round a float in place
    return __uint_as_float(cvt_tf32(x));
}

__device__ __forceinline__ void mma8(float* d, const uint32_t* a, const uint32_t* b) {
    asm volatile(
        "mma.sync.aligned.m16n8k8.row.col.f32.tf32.tf32.f32 "
        "{%0,%1,%2,%3}, {%4,%5,%6,%7}, {%8,%9}, {%0,%1,%2,%3};"
        : "+f"(d[0]), "+f"(d[1]), "+f"(d[2]), "+f"(d[3])
        : "r"(a[0]), "r"(a[1]), "r"(a[2]), "r"(a[3]), "r"(b[0]), "r"(b[1]));
}

// ---------------------------------------------------------------------------
// RoPE table
// ---------------------------------------------------------------------------
__global__ void rope_table_kernel() {
    int idx = blockIdx.x * 256 + threadIdx.x;
    int s = idx >> 5, p = idx & 31;
    double inv = 1.0 / pow(10000.0, (double)(2 * p) / 64.0);
    float ang = (float)s * (float)inv;
    g_rope[idx] = make_float2(cosf(ang), sinf(ang));
}

// ---------------------------------------------------------------------------
// mma.sync tf32 GEMM (as R4). MODE 1 additionally tf32-rounds stored q/k/v so
// the flash kernel can feed raw bits to mma with proper .rna rounding.
// ---------------------------------------------------------------------------
template <int MODE>
__global__ void __launch_bounds__(256) gemm_mma(const float* __restrict__ A,
                                                const float* __restrict__ w0,
                                                const float* __restrict__ w1,
                                                const float* __restrict__ w2,
                                                float* __restrict__ d0,
                                                float* __restrict__ d1,
                                                float* __restrict__ d2) {
    extern __shared__ float sm[];

    const int tid = threadIdx.x;
    const int lane = tid & 31, wid = tid >> 5;
    const int wm = wid >> 2, wn = wid & 3;
    const int gr = lane >> 2, gc = lane & 3;
    const int n0 = blockIdx.x * 128;
    const int m0 = blockIdx.y * 128;

    const float* W;
    float* dst;
    int rope;
    if (MODE == 1) {
        int z = blockIdx.z;
        W = z == 0 ? w0 : (z == 1 ? w1 : w2);
        dst = z == 0 ? d0 : (z == 1 ? d1 : d2);
        rope = (z < 2);
    } else {
        W = w0;
        dst = d0;
        rope = 0;
    }

    const uint32_t smb = su32(sm);

    auto fill = [&](int s, int kc) {
        uint32_t ab = smb + (uint32_t)s * STAGEB;
        uint32_t bb = ab + ABYTES;
#pragma unroll
        for (int it = 0; it < 4; it++) {
            int idx = tid + it * 256;
            int r = idx >> 3, c4 = idx & 7;
            cp16(ab + (uint32_t)(r * (ASTR * 4) + c4 * 16),
                 A + (size_t)(m0 + r) * EMBED + kc + c4 * 4);
        }
#pragma unroll
        for (int it = 0; it < 4; it++) {
            int idx = tid + it * 256;
            int r = idx >> 5, c4 = idx & 31;
            cp16(bb + (uint32_t)(r * (BSTR * 4) + c4 * 16),
                 W + (size_t)(kc + r) * EMBED + n0 + c4 * 4);
        }
        asm volatile("cp.async.commit_group;" ::: "memory");
    };

    float acc[4][4][4];
#pragma unroll
    for (int mi = 0; mi < 4; mi++)
#pragma unroll
        for (int ni = 0; ni < 4; ni++)
#pragma unroll
            for (int r = 0; r < 4; r++) acc[mi][ni][r] = 0.f;

    fill(0, 0);

    for (int i = 0; i < NCH; i++) {
        if (i + 1 < NCH) {
            fill((i + 1) & 1, (i + 1) * BK);
            asm volatile("cp.async.wait_group 1;" ::: "memory");
        } else {
            asm volatile("cp.async.wait_group 0;" ::: "memory");
        }
        __syncthreads();

        const float* Asb = sm + (i & 1) * (STAGEB / 4);
        const float* Bsb = Asb + 128 * ASTR;

#pragma unroll
        for (int ks = 0; ks < 4; ks++) {
            const int kb = ks * 8;
            uint32_t af[4][4], bf[4][2];
#pragma unroll
            for (int mi = 0; mi < 4; mi++) {
                int r0 = wm * 64 + mi * 16 + gr;
                af[mi][0] = cvt_tf32(Asb[r0 * ASTR + kb + gc]);
                af[mi][1] = cvt_tf32(Asb[(r0 + 8) * ASTR + kb + gc]);
                af[mi][2] = cvt_tf32(Asb[r0 * ASTR + kb + gc + 4]);
                af[mi][3] = cvt_tf32(Asb[(r0 + 8) * ASTR + kb + gc + 4]);
            }
#pragma unroll
            for (int ni = 0; ni < 4; ni++) {
                int c0 = wn * 32 + ni * 8 + gr;
                bf[ni][0] = cvt_tf32(Bsb[(kb + gc) * BSTR + c0]);
                bf[ni][1] = cvt_tf32(Bsb[(kb + gc + 4) * BSTR + c0]);
            }
#pragma unroll
            for (int mi = 0; mi < 4; mi++)
#pragma unroll
                for (int ni = 0; ni < 4; ni++)
                    mma8(acc[mi][ni], af[mi], bf[ni]);
        }
        __syncthreads();
    }

    if (rope) {
#pragma unroll
        for (int mi = 0; mi < 4; mi++)
#pragma unroll
            for (int h2 = 0; h2 < 2; h2++) {
                int row = m0 + wm * 64 + mi * 16 + gr + h2 * 8;
                int s = row & (SEQ - 1);
#pragma unroll
                for (int ni = 0; ni < 4; ni++) {
                    int col = n0 + wn * 32 + ni * 8 + gc * 2;
                    int p = (col & 63) >> 1;
                    float2 cs = g_rope[(size_t)s * 32 + p];
                    float e = acc[mi][ni][h2 * 2 + 0];
                    float o = acc[mi][ni][h2 * 2 + 1];
                    acc[mi][ni][h2 * 2 + 0] = e * cs.x - o * cs.y;
                    acc[mi][ni][h2 * 2 + 1] = o * cs.x + e * cs.y;
                }
            }
    }

    float* stg = sm + wid * (64 * 36);
#pragma unroll
    for (int mi = 0; mi < 4; mi++)
#pragma unroll
        for (int ni = 0; ni < 4; ni++)
#pragma unroll
            for (int h2 = 0; h2 < 2; h2++) {
                int rl = mi * 16 + gr + h2 * 8;
                int cl = ni * 8 + gc * 2;
                float v0 = acc[mi][ni][h2 * 2], v1 = acc[mi][ni][h2 * 2 + 1];
                if (MODE == 1) {  // tf32-round q/k/v at rest
                    v0 = tfr(v0);
                    v1 = tfr(v1);
                }
                *(float2*)&stg[rl * 36 + cl] = make_float2(v0, v1);
            }
    __syncwarp();

    const int lr = lane >> 3, c4 = lane & 7;
    if (MODE == 0) {
#pragma unroll
        for (int it = 0; it < 16; it++) {
            int rl = it * 4 + lr;
            float4 v = *(float4*)&stg[rl * 36 + c4 * 4];
            int row = m0 + wm * 64 + rl;
            *(float4*)&dst[(size_t)row * EMBED + n0 + wn * 32 + c4 * 4] = v;
        }
    } else {
        const int ncol = n0 + wn * 32;
        const int h = ncol >> 6, dbase = ncol & 63;
#pragma unroll
        for (int it = 0; it < 16; it++) {
            int rl = it * 4 + lr;
            float4 v = *(float4*)&stg[rl * 36 + c4 * 4];
            int row = m0 + wm * 64 + rl;
            int b = row >> 11;
            int s = row & (SEQ - 1);
            *(float4*)&dst[(((size_t)(b * HEADS + h)) * SEQ + s) * DKH + dbase + c4 * 4] = v;
        }
    }
}

// ---------------------------------------------------------------------------
// Tensor-core flash attention (tf32 mma, fp32 softmax/accum), causal.
// Block: 64 q-rows, 4 warps (16 rows each). KV tiles of 64, double-buffered.
// Q/K/V are already tf32-rounded in storage.
// ---------------------------------------------------------------------------
__global__ void __launch_bounds__(128) flash_tc(const float* __restrict__ Q,
                                                const float* __restrict__ Kk,
                                                const float* __restrict__ V,
                                                float* __restrict__ Out) {
    extern __shared__ float fs[];
    const int tid = threadIdx.x;
    const int lane = tid & 31, w = tid >> 5;
    const int gr = lane >> 2, gc = lane & 3;
    const int qi = gridDim.x - 1 - blockIdx.x;  // long blocks launch first
    const int bh = blockIdx.y;
    const int nt = qi + 1;  // kv tiles

    const float* Qb = Q + ((size_t)bh * SEQ + (size_t)qi * 64) * DKH;
    const float* Kb = Kk + (size_t)bh * SEQ * DKH;
    const float* Vb = V + (size_t)bh * SEQ * DKH;

    auto fillkv = [&](int buf, int j) {
        uint32_t kd = su32(fs + (buf ? FK1 : FK0));
        uint32_t vd = su32(fs + (buf ? FV1 : FV0));
        const float* ks = Kb + (size_t)j * 64 * DKH;
        const float* vs = Vb + (size_t)j * 64 * DKH;
#pragma unroll
        for (int it = 0; it < 8; it++) {
            int idx = tid + it * 128;
            int r = idx >> 4, c4 = idx & 15;
            cp16(kd + (uint32_t)(r * 272 + c4 * 16), ks + r * 64 + c4 * 4);
        }
#pragma unroll
        for (int it = 0; it < 8; it++) {
            int idx = tid + it * 128;
            int r = idx >> 4, c4 = idx & 15;
            cp16(vd + (uint32_t)(r * 288 + c4 * 16), vs + r * 64 + c4 * 4);
        }
        asm volatile("cp.async.commit_group;" ::: "memory");
    };

    // group 0: Q tile (into P region) + K0/V0
    {
        uint32_t qd = su32(fs + FP);
#pragma unroll
        for (int it = 0; it < 8; it++) {
            int idx = tid + it * 128;
            int r = idx >> 4, c4 = idx & 15;
            cp16(qd + (uint32_t)(r * 272 + c4 * 16), Qb + r * 64 + c4 * 4);
        }
    }
    fillkv(0, 0);
    if (nt > 1) fillkv(1, 1);

    // Q fragments (persist in registers)
    if (nt > 1)
        asm volatile("cp.async.wait_group 1;" ::: "memory");
    else
        asm volatile("cp.async.wait_group 0;" ::: "memory");
    __syncthreads();

    uint32_t qf[8][4];
    {
        const float* Pq = fs + FP;
        int r0 = w * 16 + gr;
#pragma unroll
        for (int ks = 0; ks < 8; ks++) {
            qf[ks][0] = __float_as_uint(Pq[r0 * 68 + ks * 8 + gc]);
            qf[ks][1] = __float_as_uint(Pq[(r0 + 8) * 68 + ks * 8 + gc]);
            qf[ks][2] = __float_as_uint(Pq[r0 * 68 + ks * 8 + gc + 4]);
            qf[ks][3] = __float_as_uint(Pq[(r0 + 8) * 68 + ks * 8 + gc + 4]);
        }
    }
    __syncthreads();  // P region now reusable

    float miA = -1e30f, miB = -1e30f, liA = 0.f, liB = 0.f;
    float oacc[8][4];
#pragma unroll
    for (int n8 = 0; n8 < 8; n8++)
#pragma unroll
        for (int r = 0; r < 4; r++) oacc[n8][r] = 0.f;

    float* Pw = fs + FP + w * (16 * 68);

    for (int j = 0; j < nt; j++) {
        if (j <= nt - 2)
            asm volatile("cp.async.wait_group 1;" ::: "memory");
        else
            asm volatile("cp.async.wait_group 0;" ::: "memory");
        __syncthreads();

        const float* Ks = fs + ((j & 1) ? FK1 : FK0);
        const float* Vs = fs + ((j & 1) ? FV1 : FV0);

        // S = Q K^T (16x64 per warp)
        float sacc[8][4];
#pragma unroll
        for (int n8 = 0; n8 < 8; n8++)
#pragma unroll
            for (int r = 0; r < 4; r++) sacc[n8][r] = 0.f;

#pragma unroll
        for (int ks = 0; ks < 8; ks++) {
#pragma unroll
            for (int n8 = 0; n8 < 8; n8++) {
                uint32_t bf[2];
                bf[0] = __float_as_uint(Ks[(n8 * 8 + gr) * 68 + ks * 8 + gc]);
                bf[1] = __float_as_uint(Ks[(n8 * 8 + gr) * 68 + ks * 8 + gc + 4]);
                mma8(sacc[n8], qf[ks], bf);
            }
        }

        // scale + causal mask (diagonal tile only)
        if (j == nt - 1) {
            int r0 = qi * 64 + w * 16 + gr;
#pragma unroll
            for (int n8 = 0; n8 < 8; n8++) {
                int c = j * 64 + n8 * 8 + 2 * gc;
                sacc[n8][0] = (c > r0) ? -1e30f : sacc[n8][0] * 0.125f;
                sacc[n8][1] = (c + 1 > r0) ? -1e30f : sacc[n8][1] * 0.125f;
                sacc[n8][2] = (c > r0 + 8) ? -1e30f : sacc[n8][2] * 0.125f;
                sacc[n8][3] = (c + 1 > r0 + 8) ? -1e30f : sacc[n8][3] * 0.125f;
            }
        } else {
#pragma unroll
            for (int n8 = 0; n8 < 8; n8++)
#pragma unroll
                for (int r = 0; r < 4; r++) sacc[n8][r] *= 0.125f;
        }

        // online softmax (rows gr and gr+8)
        float mA = -1e30f, mB = -1e30f;
#pragma unroll
        for (int n8 = 0; n8 < 8; n8++) {
            mA = fmaxf(mA, fmaxf(sacc[n8][0], sacc[n8][1]));
            mB = fmaxf(mB, fmaxf(sacc[n8][2], sacc[n8][3]));
        }
        mA = fmaxf(mA, __shfl_xor_sync(0xffffffffu, mA, 1));
        mA = fmaxf(mA, __shfl_xor_sync(0xffffffffu, mA, 2));
        mB = fmaxf(mB, __shfl_xor_sync(0xffffffffu, mB, 1));
        mB = fmaxf(mB, __shfl_xor_sync(0xffffffffu, mB, 2));

        float mnA = fmaxf(miA, mA), mnB = fmaxf(miB, mB);
        float aA = __expf(miA - mnA), aB = __expf(miB - mnB);
        float sA = 0.f, sB = 0.f;
#pragma unroll
        for (int n8 = 0; n8 < 8; n8++) {
            float p0 = __expf(sacc[n8][0] - mnA);
            float p1 = __expf(sacc[n8][1] - mnA);
            float p2 = __expf(sacc[n8][2] - mnB);
            float p3 = __expf(sacc[n8][3] - mnB);
            sA += p0 + p1;
            sB += p2 + p3;
            *(float2*)&Pw[gr * 68 + n8 * 8 + 2 * gc] = make_float2(tfr(p0), tfr(p1));
            *(float2*)&Pw[(gr + 8) * 68 + n8 * 8 + 2 * gc] = make_float2(tfr(p2), tfr(p3));
        }
        sA += __shfl_xor_sync(0xffffffffu, sA, 1);
        sA += __shfl_xor_sync(0xffffffffu, sA, 2);
        sB += __shfl_xor_sync(0xffffffffu, sB, 1);
        sB += __shfl_xor_sync(0xffffffffu, sB, 2);
        liA = liA * aA + sA;
        liB = liB * aB + sB;
        miA = mnA;
        miB = mnB;
#pragma unroll
        for (int n8 = 0; n8 < 8; n8++) {
            oacc[n8][0] *= aA;
            oacc[n8][1] *= aA;
            oacc[n8][2] *= aB;
            oacc[n8][3] *= aB;
        }
        __syncwarp();

        // O += P V (16x64 per warp)
#pragma unroll
        for (int ks = 0; ks < 8; ks++) {
            uint32_t af[4];
            af[0] = __float_as_uint(Pw[gr * 68 + ks * 8 + gc]);
            af[1] = __float_as_uint(Pw[(gr + 8) * 68 + ks * 8 + gc]);
            af[2] = __float_as_uint(Pw[gr * 68 + ks * 8 + gc + 4]);
            af[3] = __float_as_uint(Pw[(gr + 8) * 68 + ks * 8 + gc + 4]);
#pragma unroll
            for (int n8 = 0; n8 < 8; n8++) {
                uint32_t bf[2];
                bf[0] = __float_as_uint(Vs[(ks * 8 + gc) * 72 + n8 * 8 + gr]);
                bf[1] = __float_as_uint(Vs[(ks * 8 + gc + 4) * 72 + n8 * 8 + gr]);
                mma8(oacc[n8], af, bf);
            }
        }

        __syncthreads();  // all warps done with K/V buffers
        if (j + 2 < nt) fillkv(j & 1, j + 2);
    }

    // epilogue: normalize, write [B,S,E]
    const int b = bh >> 4, h = bh & 15;
    const int row = qi * 64 + w * 16 + gr;
    float invA = 1.f / liA, invB = 1.f / liB;
    float* o0 = Out + ((size_t)b * SEQ + row) * EMBED + h * 64;
    float* o1 = Out + ((size_t)b * SEQ + row + 8) * EMBED + h * 64;
#pragma unroll
    for (int n8 = 0; n8 < 8; n8++) {
        *(float2*)&o0[n8 * 8 + 2 * gc] =
            make_float2(oacc[n8][0] * invA, oacc[n8][1] * invA);
        *(float2*)&o1[n8 * 8 + 2 * gc] =
            make_float2(oacc[n8][2] * invB, oacc[n8][3] * invB);
    }
}

extern "C" void kernel_launch(void* const* d_in, const int* in_sizes, int n_in,
                              void* d_out, int out_size) {
    (void)in_sizes;
    (void)n_in;
    (void)out_size;
    const float* x = (const float*)d_in[0];
    const float* wq = (const float*)d_in[1];
    const float* wk = (const float*)d_in[2];
    const float* wv = (const float*)d_in[3];
    const float* wo = (const float*)d_in[4];
    float* out = (float*)d_out;

    float *q, *k, *v, *attn;
    cudaGetSymbolAddress((void**)&q, g_q);
    cudaGetSymbolAddress((void**)&k, g_k);
    cudaGetSymbolAddress((void**)&v, g_v);
    cudaGetSymbolAddress((void**)&attn, g_attn);

    cudaFuncSetAttribute(gemm_mma<1>, cudaFuncAttributeMaxDynamicSharedMemorySize, GSMEM);
    cudaFuncSetAttribute(gemm_mma<0>, cudaFuncAttributeMaxDynamicSharedMemorySize, GSMEM);
    cudaFuncSetAttribute(flash_tc, cudaFuncAttributeMaxDynamicSharedMemorySize, FSMEM);

    rope_table_kernel<<<SEQ * 32 / 256, 256>>>();
    gemm_mma<1><<<dim3(EMBED / 128, MTOT / 128, 3), 256, GSMEM>>>(x, wq, wk, wv, q, k, v);
    flash_tc<<<dim3(SEQ / 64, BATCH * HEADS), 128, FSMEM>>>(q, k, v, attn);
    gemm_mma<0><<<dim3(EMBED / 128, MTOT / 128, 1), 256, GSMEM>>>(attn, wo, nullptr, nullptr,
                                                                  out, nullptr, nullptr);
}